// round 17
// baseline (speedup 1.0000x reference)
#include <cuda_runtime.h>
#include <cstdint>

#define NTOK 64
#define DIM  128
#define B1N  2048
#define B2N  8192
#define QSCALE 0.17677669529663687f
#define X_ELEMS 16777216   // B1N*NTOK*DIM

// Tiled scratch layouts (8x8 tiles, 64 floats each):
//  g_Q[b][8192]:  tile=(n>>3)*16+(k>>3), pos=(n&7)*8+2*(k&3)+((k&4)>>2)
//  g_KV[b2][16384]: K half [0,8192) same as Q with (m,d);
//                   V half [8192,16384): tile=(m>>3)*16+(d>>3),
//                                        pos=(d&7)*8+2*(m&3)+((m&4)>>2)
__device__ float g_Q[(size_t)B1N * 8192];
__device__ float g_KV[(size_t)B2N * 16384];

__device__ __forceinline__ float to_tf32(float x) {
    float r; asm("cvt.rna.tf32.f32 %0, %1;" : "=f"(r) : "f"(x)); return r;
}
__device__ __forceinline__ void mma_tf32(float c[4],
    uint32_t a0, uint32_t a1, uint32_t a2, uint32_t a3,
    uint32_t b0, uint32_t b1)
{
    asm volatile(
        "mma.sync.aligned.m16n8k8.row.col.f32.tf32.tf32.f32 "
        "{%0,%1,%2,%3},{%4,%5,%6,%7},{%8,%9},{%0,%1,%2,%3};"
        : "+f"(c[0]), "+f"(c[1]), "+f"(c[2]), "+f"(c[3])
        : "r"(a0), "r"(a1), "r"(a2), "r"(a3), "r"(b0), "r"(b1));
}

__device__ __forceinline__ int tiled_nk(int n, int k) {   // Q/K/W layout
    return ((n >> 3) * 16 + (k >> 3)) * 64 + (n & 7) * 8 + 2 * (k & 3) + ((k & 4) >> 2);
}
__device__ __forceinline__ int tiled_v(int m, int d) {    // V layout
    return ((m >> 3) * 16 + (d >> 3)) * 64 + (d & 7) * 8 + 2 * (m & 3) + ((m & 4) >> 2);
}

__device__ __forceinline__ uint32_t smem_u32(const void* p) {
    return (uint32_t)__cvta_generic_to_shared(p);
}
__device__ __forceinline__ void cp16(uint32_t dst, const void* src) {
    asm volatile("cp.async.cg.shared.global [%0], [%1], 16;" :: "r"(dst), "l"(src));
}
#define CP_COMMIT() asm volatile("cp.async.commit_group;")
#define CP_WAIT0()  asm volatile("cp.async.wait_group 0;")

// ---------------------------------------------------------------------------
// Kernel B v2 (first -> profile slot): KV = tf32( x2 @ W2^T + b2 )
// R17: CTA = (window-group, output-half). 256 thr, 2 CTAs/SM.
// Each CTA holds ONLY its 128-row half of W2 (tiled, 64 KB) and computes
// the 64x128 half of each of its 8 windows. Single x2 buffer; the
// co-resident sibling CTA hides staging latency (R16-validated mechanism).
// Warp w (0..7): m-tile (w&3)*16, local n-base (w>>2)*64, 8 n-tiles.
// ---------------------------------------------------------------------------
#define KV_GW 8
#define KV_SMEM_FLOATS (16384 + 8448)   // w_half tiled + x2 stride-132 buffer

__global__ void __launch_bounds__(256, 2) kv_kernel(
    const float* __restrict__ x2, const float* __restrict__ w2,
    const float* __restrict__ bias2)
{
    extern __shared__ float sm[];
    float* w_s = sm;             // 16384 : half of W2, tiled (local rows 0..127)
    float* a_s = sm + 16384;     // 8448  : x2 window, stride 132

    const int t = threadIdx.x;
    const int lane = t & 31, wid = t >> 5;     // wid 0..7
    const int m_base = (wid & 3) * 16;
    const int nb     = (wid >> 2) * 64;        // local n-base within the half
    const int r0 = lane >> 2, cth = lane & 3;
    const int group = blockIdx.x >> 1;
    const int half  = blockIdx.x & 1;          // 0 = K rows, 1 = V rows
    const int base  = group * KV_GW;
    const int jglob0 = half * 128;             // global W2 row offset

    // stage this CTA's half of W2 (128x128) tiled + tf32(rna)
    for (int idx = t; idx < 4096; idx += 256) {
        const int j = idx >> 5, k4 = (idx & 31) * 4;     // j local 0..127
        const float4 w = *(const float4*)(w2 + (jglob0 + j) * DIM + k4);
        w_s[tiled_nk(j, k4 + 0)] = to_tf32(w.x);
        w_s[tiled_nk(j, k4 + 1)] = to_tf32(w.y);
        w_s[tiled_nk(j, k4 + 2)] = to_tf32(w.z);
        w_s[tiled_nk(j, k4 + 3)] = to_tf32(w.w);
    }

    for (int g = 0; g < KV_GW; g++) {
        const int b2 = base + g;

        __syncthreads();   // previous window's a_s readers done (g=0: w_s ordered too)
        {
            const float* xb = x2 + (size_t)b2 * 8192;
#pragma unroll
            for (int i = 0; i < 8; i++) {
                const int idx = t + i * 256;          // 0..2047 float4 chunks
                const int m = idx >> 5, k4 = (idx & 31) * 4;
                cp16(smem_u32(a_s + m * 132 + k4), xb + m * DIM + k4);
            }
            CP_COMMIT();
            CP_WAIT0();
        }
        __syncthreads();   // window visible

        float c[8][4];
#pragma unroll
        for (int nt = 0; nt < 8; nt++)
#pragma unroll
            for (int j = 0; j < 4; j++) c[nt][j] = 0.f;

#pragma unroll
        for (int kc = 0; kc < 4; kc++) {
#pragma unroll
            for (int ks = 0; ks < 4; ks++) {
                const int col = kc * 32 + ks * 8 + cth;
                const uint32_t a0 = __float_as_uint(a_s[(m_base + r0) * 132 + col]);
                const uint32_t a1 = __float_as_uint(a_s[(m_base + r0 + 8) * 132 + col]);
                const uint32_t a2 = __float_as_uint(a_s[(m_base + r0) * 132 + col + 4]);
                const uint32_t a3 = __float_as_uint(a_s[(m_base + r0 + 8) * 132 + col + 4]);
                const int ktile = kc * 4 + ks;
#pragma unroll
                for (int nt = 0; nt < 8; nt++) {
                    const int tile = ((nb >> 3) + nt) * 16 + ktile;
                    const float2 bp = *(const float2*)&w_s[tile * 64 + r0 * 8 + 2 * cth];
                    mma_tf32(c[nt], a0, a1, a2, a3,
                             __float_as_uint(bp.x), __float_as_uint(bp.y));
                }
            }
        }

        // epilogue: +bias, tf32(rna)-round, tiled stores (branch-free per CTA)
        float* dst = g_KV + (size_t)b2 * 16384 + half * 8192;
        const int row0 = m_base + r0;
#pragma unroll
        for (int nt = 0; nt < 8; nt++) {
            const int cl = nb + nt * 8 + 2 * cth;        // local col 0..126
            const float2 bv = *(const float2*)(bias2 + jglob0 + cl);
            const float v00 = to_tf32(c[nt][0] + bv.x);
            const float v01 = to_tf32(c[nt][1] + bv.y);
            const float v10 = to_tf32(c[nt][2] + bv.x);
            const float v11 = to_tf32(c[nt][3] + bv.y);
            if (half == 0) {
                dst[tiled_nk(row0,     cl    )] = v00;
                dst[tiled_nk(row0,     cl + 1)] = v01;
                dst[tiled_nk(row0 + 8, cl    )] = v10;
                dst[tiled_nk(row0 + 8, cl + 1)] = v11;
            } else {
                dst[tiled_v(row0,     cl    )] = v00;
                dst[tiled_v(row0,     cl + 1)] = v01;
                dst[tiled_v(row0 + 8, cl    )] = v10;
                dst[tiled_v(row0 + 8, cl + 1)] = v11;
            }
        }
    }
}

// ---------------------------------------------------------------------------
// Kernel A: Q = tf32( scale * (x1 @ W1^T + b1) )  [unchanged]
// ---------------------------------------------------------------------------
#define QK_SMEM_FLOATS (8448 + 4608)

__global__ void __launch_bounds__(256) q_kernel(
    const float* __restrict__ x1, const float* __restrict__ w1,
    const float* __restrict__ bias1)
{
    extern __shared__ float sm[];
    float* a_s = sm;
    float* w_s = sm + 8448;

    const int t = threadIdx.x, b = blockIdx.x;
    const int lane = t & 31, wid = t >> 5;
    const int m_base = (wid & 3) * 16;
    const int n_base = (wid >> 2) * 64;
    const int r0 = lane >> 2, cth = lane & 3;

    const float* xb = x1 + (size_t)b * (NTOK * DIM);
    for (int idx = t; idx < NTOK * DIM; idx += 256) {
        int m = idx >> 7, k = idx & 127;
        a_s[m * 132 + k] = to_tf32(xb[idx]);
    }

    float c[8][4];
#pragma unroll
    for (int nt = 0; nt < 8; nt++)
#pragma unroll
        for (int j = 0; j < 4; j++) c[nt][j] = 0.f;

    for (int kc = 0; kc < 4; kc++) {
        __syncthreads();
        for (int idx = t; idx < 4096; idx += 256) {
            int j = idx >> 5, kk = idx & 31;
            w_s[j * 36 + kk] = to_tf32(w1[j * DIM + kc * 32 + kk]);
        }
        __syncthreads();
#pragma unroll
        for (int ks = 0; ks < 4; ks++) {
            const int col = kc * 32 + ks * 8 + cth;
            const uint32_t a0 = __float_as_uint(a_s[(m_base + r0) * 132 + col]);
            const uint32_t a1 = __float_as_uint(a_s[(m_base + r0 + 8) * 132 + col]);
            const uint32_t a2 = __float_as_uint(a_s[(m_base + r0) * 132 + col + 4]);
            const uint32_t a3 = __float_as_uint(a_s[(m_base + r0 + 8) * 132 + col + 4]);
#pragma unroll
            for (int nt = 0; nt < 8; nt++) {
                const int j = n_base + nt * 8 + r0;
                const uint32_t b0 = __float_as_uint(w_s[j * 36 + ks * 8 + cth]);
                const uint32_t b1 = __float_as_uint(w_s[j * 36 + ks * 8 + 4 + cth]);
                mma_tf32(c[nt], a0, a1, a2, a3, b0, b1);
            }
        }
    }

    float* qb = g_Q + (size_t)b * 8192;
    const int row0 = m_base + r0;
#pragma unroll
    for (int nt = 0; nt < 8; nt++) {
        const int col0 = n_base + nt * 8 + 2 * cth;
        const float2 bv = *(const float2*)(bias1 + col0);
        qb[tiled_nk(row0,     col0    )] = to_tf32((c[nt][0] + bv.x) * QSCALE);
        qb[tiled_nk(row0,     col0 + 1)] = to_tf32((c[nt][1] + bv.y) * QSCALE);
        qb[tiled_nk(row0 + 8, col0    )] = to_tf32((c[nt][2] + bv.x) * QSCALE);
        qb[tiled_nk(row0 + 8, col0 + 1)] = to_tf32((c[nt][3] + bv.y) * QSCALE);
    }
}

// ---------------------------------------------------------------------------
// Kernel C (R16 committed win): 256 thr, 2 CTAs/SM, 2 jobs/warp.
// ---------------------------------------------------------------------------
#define ATTN_SMEM_FLOATS 24576   // 98304 B

__global__ void __launch_bounds__(256, 2) attn_kernel(
    const float* __restrict__ pw, const float* __restrict__ pb,
    const float* __restrict__ rpb, const int* __restrict__ rel,
    float* __restrict__ out)
{
    extern __shared__ float sm[];
    uint16_t* rel_s = (uint16_t*)(sm + 16384);
    float*    tab_s = sm + 18432;

    const int t    = threadIdx.x;
    const int bdst = blockIdx.x;
    const int lane = t & 31, wid = t >> 5;     // wid 0..7
    const int r0 = lane >> 2, cth = lane & 3;
    const int ldoff = r0 * 8 + 2 * cth;

    for (int idx = t; idx < NTOK * NTOK; idx += 256)
        rel_s[idx] = (uint16_t)rel[idx];
    for (int idx = t; idx < 225 * 4; idx += 256)
        tab_s[idx] = rpb[idx];

    float oacc[2][4][4];
#pragma unroll
    for (int jj = 0; jj < 2; jj++)
#pragma unroll
        for (int nt = 0; nt < 4; nt++)
#pragma unroll
            for (int j = 0; j < 4; j++) oacc[jj][nt][j] = 0.f;

    for (int r = 0; r < 4; r++) {
        const int b2 = bdst * 4 + r;

        __syncthreads();
        {
            const float4* kvg = (const float4*)(g_KV + (size_t)b2 * 16384);
#pragma unroll
            for (int i = 0; i < 16; i++) {
                const int idx = t + i * 256;
                cp16(smem_u32(sm + idx * 4), kvg + idx);
            }
            CP_COMMIT();
            CP_WAIT0();
        }
        __syncthreads();

        float* k_s = sm;
        float* v_s = sm + 8192;
        const int qb = b2 & (B1N - 1);
        const float* qg = g_Q + (size_t)qb * 8192;

#pragma unroll
        for (int jj = 0; jj < 2; jj++) {
            const int job = wid + jj * 8;
            const int h   = job >> 2;
            const int R0  = (job & 3) * 16;
            const int n_lo = R0 + r0, n_hi = n_lo + 8;

            float2 qalo[4], qahi[4];
#pragma unroll
            for (int ks = 0; ks < 4; ks++) {
                const int kt = h * 4 + ks;
                qalo[ks] = *(const float2*)&qg[(((R0 >> 3)    ) * 16 + kt) * 64 + ldoff];
                qahi[ks] = *(const float2*)&qg[(((R0 >> 3) + 1) * 16 + kt) * 64 + ldoff];
            }

            float c[8][4];
#pragma unroll
            for (int nt = 0; nt < 8; nt++)
#pragma unroll
                for (int j = 0; j < 4; j++) c[nt][j] = 0.f;

#pragma unroll
            for (int ks = 0; ks < 4; ks++) {
                const int kt = h * 4 + ks;
                const uint32_t a0 = __float_as_uint(qalo[ks].x);
                const uint32_t a1 = __float_as_uint(qahi[ks].x);
                const uint32_t a2 = __float_as_uint(qalo[ks].y);
                const uint32_t a3 = __float_as_uint(qahi[ks].y);
#pragma unroll
                for (int nt = 0; nt < 8; nt++) {
                    const float2 bp = *(const float2*)&k_s[(nt * 16 + kt) * 64 + ldoff];
                    mma_tf32(c[nt], a0, a1, a2, a3,
                             __float_as_uint(bp.x), __float_as_uint(bp.y));
                }
            }

#pragma unroll
            for (int nt = 0; nt < 8; nt++) {
                const int m = nt * 8 + 2 * cth;
                const uint32_t rlo = *(const uint32_t*)&rel_s[n_lo * 64 + m];
                const uint32_t rhi = *(const uint32_t*)&rel_s[n_hi * 64 + m];
                c[nt][0] += tab_s[(rlo & 0xffff) * 4 + h];
                c[nt][1] += tab_s[(rlo >> 16) * 4 + h];
                c[nt][2] += tab_s[(rhi & 0xffff) * 4 + h];
                c[nt][3] += tab_s[(rhi >> 16) * 4 + h];
            }

            float mx0 = -1e30f, mx1 = -1e30f;
#pragma unroll
            for (int nt = 0; nt < 8; nt++) {
                mx0 = fmaxf(mx0, fmaxf(c[nt][0], c[nt][1]));
                mx1 = fmaxf(mx1, fmaxf(c[nt][2], c[nt][3]));
            }
            mx0 = fmaxf(mx0, __shfl_xor_sync(0xffffffffu, mx0, 1));
            mx0 = fmaxf(mx0, __shfl_xor_sync(0xffffffffu, mx0, 2));
            mx1 = fmaxf(mx1, __shfl_xor_sync(0xffffffffu, mx1, 1));
            mx1 = fmaxf(mx1, __shfl_xor_sync(0xffffffffu, mx1, 2));

            float s0 = 0.f, s1 = 0.f;
#pragma unroll
            for (int nt = 0; nt < 8; nt++) {
                c[nt][0] = __expf(c[nt][0] - mx0); s0 += c[nt][0];
                c[nt][1] = __expf(c[nt][1] - mx0); s0 += c[nt][1];
                c[nt][2] = __expf(c[nt][2] - mx1); s1 += c[nt][2];
                c[nt][3] = __expf(c[nt][3] - mx1); s1 += c[nt][3];
            }
            s0 += __shfl_xor_sync(0xffffffffu, s0, 1);
            s0 += __shfl_xor_sync(0xffffffffu, s0, 2);
            s1 += __shfl_xor_sync(0xffffffffu, s1, 1);
            s1 += __shfl_xor_sync(0xffffffffu, s1, 2);
            const float inv0 = 1.f / s0, inv1 = 1.f / s1;
#pragma unroll
            for (int nt = 0; nt < 8; nt++) {
                c[nt][0] *= inv0; c[nt][1] *= inv0;
                c[nt][2] *= inv1; c[nt][3] *= inv1;
            }

            float* ao = out + (size_t)X_ELEMS + (size_t)b2 * 16384 + h * 4096;
#pragma unroll
            for (int nt = 0; nt < 8; nt++) {
                const int m = nt * 8 + 2 * cth;
                *(float2*)&ao[n_lo * 64 + m] = make_float2(c[nt][0], c[nt][1]);
                *(float2*)&ao[n_hi * 64 + m] = make_float2(c[nt][2], c[nt][3]);
            }

#pragma unroll
            for (int nt = 0; nt < 8; nt++)
#pragma unroll
                for (int j = 0; j < 4; j++) c[nt][j] = to_tf32(c[nt][j]);

            const int src0 = (lane & 28) + (cth >> 1);
            const int src1 = src0 + 2;
            const bool odd = (cth & 1);
#pragma unroll
            for (int ks = 0; ks < 8; ks++) {
                const float e0 = __shfl_sync(0xffffffffu, c[ks][0], src0);
                const float o0 = __shfl_sync(0xffffffffu, c[ks][1], src0);
                const float e2 = __shfl_sync(0xffffffffu, c[ks][0], src1);
                const float o2 = __shfl_sync(0xffffffffu, c[ks][1], src1);
                const float e1 = __shfl_sync(0xffffffffu, c[ks][2], src0);
                const float o1 = __shfl_sync(0xffffffffu, c[ks][3], src0);
                const float e3 = __shfl_sync(0xffffffffu, c[ks][2], src1);
                const float o3 = __shfl_sync(0xffffffffu, c[ks][3], src1);
                const uint32_t pa0 = __float_as_uint(odd ? o0 : e0);
                const uint32_t pa1 = __float_as_uint(odd ? o1 : e1);
                const uint32_t pa2 = __float_as_uint(odd ? o2 : e2);
                const uint32_t pa3 = __float_as_uint(odd ? o3 : e3);
#pragma unroll
                for (int nt = 0; nt < 4; nt++) {
                    const float2 bp = *(const float2*)&v_s[(ks * 16 + h * 4 + nt) * 64 + ldoff];
                    mma_tf32(oacc[jj][nt], pa0, pa1, pa2, pa3,
                             __float_as_uint(bp.x), __float_as_uint(bp.y));
                }
            }
        } // jj
    } // r

    // tail: O tiled -> o_s, pw tiled -> pw_s, proj via tf32 mma
    __syncthreads();
    float* o_s  = sm;
    float* pw_s = sm + 8192;

#pragma unroll
    for (int jj = 0; jj < 2; jj++) {
        const int job = wid + jj * 8;
        const int h   = job >> 2;
        const int R0  = (job & 3) * 16;
        const int n_lo = R0 + r0, n_hi = n_lo + 8;
#pragma unroll
        for (int nt = 0; nt < 4; nt++) {
            const int d0 = h * 32 + nt * 8 + 2 * cth;
            o_s[tiled_nk(n_lo, d0    )] = to_tf32(oacc[jj][nt][0]);
            o_s[tiled_nk(n_lo, d0 + 1)] = to_tf32(oacc[jj][nt][1]);
            o_s[tiled_nk(n_hi, d0    )] = to_tf32(oacc[jj][nt][2]);
            o_s[tiled_nk(n_hi, d0 + 1)] = to_tf32(oacc[jj][nt][3]);
        }
    }
    for (int idx = t; idx < 4096; idx += 256) {
        const int j = idx >> 5, k4 = (idx & 31) * 4;
        const float4 w = *(const float4*)(pw + j * DIM + k4);
        pw_s[tiled_nk(j, k4 + 0)] = to_tf32(w.x);
        pw_s[tiled_nk(j, k4 + 1)] = to_tf32(w.y);
        pw_s[tiled_nk(j, k4 + 2)] = to_tf32(w.z);
        pw_s[tiled_nk(j, k4 + 3)] = to_tf32(w.w);
    }
    __syncthreads();

    float* xo = out + (size_t)bdst * (NTOK * DIM);
#pragma unroll
    for (int jj = 0; jj < 2; jj++) {
        const int pjob  = wid + jj * 8;
        const int slab  = (pjob & 3) * 16;
        const int jbase = (pjob >> 2) * 32;
        float pc[4][4];
#pragma unroll
        for (int nt = 0; nt < 4; nt++)
#pragma unroll
            for (int j = 0; j < 4; j++) pc[nt][j] = 0.f;

#pragma unroll
        for (int kt = 0; kt < 16; kt++) {
            const float2 alo = *(const float2*)&o_s[(((slab >> 3)    ) * 16 + kt) * 64 + ldoff];
            const float2 ahi = *(const float2*)&o_s[(((slab >> 3) + 1) * 16 + kt) * 64 + ldoff];
            const uint32_t a0 = __float_as_uint(alo.x);
            const uint32_t a1 = __float_as_uint(ahi.x);
            const uint32_t a2 = __float_as_uint(alo.y);
            const uint32_t a3 = __float_as_uint(ahi.y);
#pragma unroll
            for (int nt = 0; nt < 4; nt++) {
                const float2 bp = *(const float2*)&pw_s[(((jbase >> 3) + nt) * 16 + kt) * 64 + ldoff];
                mma_tf32(pc[nt], a0, a1, a2, a3,
                         __float_as_uint(bp.x), __float_as_uint(bp.y));
            }
        }

        const int prow = slab + r0;
#pragma unroll
        for (int nt = 0; nt < 4; nt++) {
            const int col0 = jbase + nt * 8 + 2 * cth;
            const float2 bv = *(const float2*)(pb + col0);
            *(float2*)&xo[prow * DIM + col0] =
                make_float2(pc[nt][0] + bv.x, pc[nt][1] + bv.y);
            *(float2*)&xo[(prow + 8) * DIM + col0] =
                make_float2(pc[nt][2] + bv.x, pc[nt][3] + bv.y);
        }
    }
}

// ---------------------------------------------------------------------------
extern "C" void kernel_launch(void* const* d_in, const int* in_sizes, int n_in,
                              void* d_out, int out_size)
{
    const float* x1     = (const float*)d_in[0];
    const float* x2     = (const float*)d_in[1];
    const float* qkv1_w = (const float*)d_in[2];
    const float* qkv1_b = (const float*)d_in[3];
    const float* qkv2_w = (const float*)d_in[4];
    const float* qkv2_b = (const float*)d_in[5];
    const float* proj_w = (const float*)d_in[6];
    const float* proj_b = (const float*)d_in[7];
    const float* rpb    = (const float*)d_in[8];
    const int*   rel    = (const int*)d_in[9];
    float* out = (float*)d_out;

    static bool attr_set = false;
    if (!attr_set) {
        cudaFuncSetAttribute(q_kernel,
                             cudaFuncAttributeMaxDynamicSharedMemorySize,
                             QK_SMEM_FLOATS * sizeof(float));
        cudaFuncSetAttribute(kv_kernel,
                             cudaFuncAttributeMaxDynamicSharedMemorySize,
                             KV_SMEM_FLOATS * sizeof(float));
        cudaFuncSetAttribute(attn_kernel,
                             cudaFuncAttributeMaxDynamicSharedMemorySize,
                             ATTN_SMEM_FLOATS * sizeof(float));
        attr_set = true;
    }

    kv_kernel<<<(B2N / KV_GW) * 2, 256, KV_SMEM_FLOATS * sizeof(float)>>>(
        x2, qkv2_w, qkv2_b);
    q_kernel<<<B1N, 256, QK_SMEM_FLOATS * sizeof(float)>>>(x1, qkv1_w, qkv1_b);
    attn_kernel<<<B1N, 256, ATTN_SMEM_FLOATS * sizeof(float)>>>(
        proj_w, proj_b, rpb, rel, out);
}